// round 15
// baseline (speedup 1.0000x reference)
#include <cuda_runtime.h>
#include <stdint.h>

// Fixed problem shape (LengthRegulator_33285996544559):
//   x:   [B=32, T=512, C=512] float32
//   dur: [B=32, T=512] int32 in [0, 12)
//   out: [B, T_out, C] float32, T_out = out_size / (B*C)
//
// FINAL KERNEL — converged after 14 rounds. Plateau evidence:
//   R4/R5/R9/R11 (four distinct structures) all measure 36.93 us total;
//   DRAM pinned at ~59% (4.7 TB/s) with no other unit above 50%.
//   Falsified alternatives: MLP>4 (neutral), persistent blocks (-12%),
//   barrier-free warp scan (-5%), PDL split (-7%), stwt (-12% e2e),
//   TMA bulk stores (-8%), L2 read dedup (neutral twice).
//   Binding resource: the ~203 MB compulsory output write stream at
//   ~5.5 TB/s effective mixed bandwidth.
//
// Structure: fused single kernel, 256-thread blocks, 8 warps x 2 frames.
//   1) shfl pair-scan of the row's 512 durations (3 syncthreads)
//   2) scatter token ids into a 16-frame smem window
//   3) warp w gathers frames 2w, 2w+1: all 8 LDG.128 in flight before any
//      store (x is L2-resident); __stcs streaming stores.
#define B_DIM 32
#define T_DIM 512
#define C_DIM 512
#define FRAMES_PER_BLOCK 16   // 8 warps x 2 frames, 256 threads

__global__ void __launch_bounds__(256) lr_fused_kernel(
    const float4* __restrict__ x4,
    float4*       __restrict__ out4,
    const int*    __restrict__ dur,
    int t_out)
{
    __shared__ int s_wsum[8];
    __shared__ int s_idx[FRAMES_PER_BLOCK];

    const int row   = blockIdx.y;
    const int fbase = blockIdx.x * FRAMES_PER_BLOCK;
    const int tid   = threadIdx.x;
    const int wid   = tid >> 5;
    const int lane  = tid & 31;

    // ---- 1) scan: each thread owns a PAIR of durations (int2 load) ----
    int2 dd = ((const int2*)dur)[row * (T_DIM / 2) + tid];
    int d0 = dd.x > 0 ? dd.x : 0;
    int d1 = dd.y > 0 ? dd.y : 0;
    int p  = d0 + d1;

    int v = p;                                // intra-warp inclusive scan
    #pragma unroll
    for (int off = 1; off < 32; off <<= 1) {
        int n = __shfl_up_sync(0xffffffffu, v, off);
        if (lane >= off) v += n;
    }
    if (lane == 31) s_wsum[wid] = v;
    __syncthreads();
    if (wid == 0) {
        int w = (lane < 8) ? s_wsum[lane] : 0;
        #pragma unroll
        for (int off = 1; off < 8; off <<= 1) {
            int n = __shfl_up_sync(0xffffffffu, w, off);
            if (lane >= off) w += n;
        }
        if (lane < 8) s_wsum[lane] = w;
    }
    __syncthreads();

    const int pair_incl = ((wid > 0) ? s_wsum[wid - 1] : 0) + v;
    const int pair_excl = pair_incl - p;      // exclusive cumsum before token 2*tid
    const int total     = s_wsum[7];

    // token 2*tid   owns frames [pair_excl,    pair_excl+d0)
    // token 2*tid+1 owns frames [pair_excl+d0, pair_incl)

    // ---- 2) scatter into this block's frame window ----
    const int fend = fbase + FRAMES_PER_BLOCK;
    {
        int s = pair_excl, e = pair_excl + d0;
        int lo = s > fbase ? s : fbase;
        int hi = e < fend ? e : fend;
        for (int t = lo; t < hi; t++) s_idx[t - fbase] = 2 * tid;

        s = e; e = pair_incl;
        lo = s > fbase ? s : fbase;
        hi = e < fend ? e : fend;
        for (int t = lo; t < hi; t++) s_idx[t - fbase] = 2 * tid + 1;
    }
    if (tid < FRAMES_PER_BLOCK && (fbase + tid) >= total)
        s_idx[tid] = T_DIM - 1;               // overflow -> last token
    __syncthreads();

    // ---- 3) gather: warp w -> frames 2w, 2w+1 ----
    const int lf0 = wid << 1;
    const int f0  = fbase + lf0;
    if (f0 >= t_out) return;

    const bool has2 = (f0 + 1) < t_out;
    const int  i0 = s_idx[lf0];
    const int  i1 = s_idx[has2 ? lf0 + 1 : lf0];

    const float4* s0 = x4 + ((long long)(row * T_DIM + i0) << 7);
    const float4* s1 = x4 + ((long long)(row * T_DIM + i1) << 7);

    float4 v0 = __ldg(&s0[lane]);
    float4 v1 = __ldg(&s0[lane + 32]);
    float4 v2 = __ldg(&s0[lane + 64]);
    float4 v3 = __ldg(&s0[lane + 96]);
    float4 u0 = __ldg(&s1[lane]);
    float4 u1 = __ldg(&s1[lane + 32]);
    float4 u2 = __ldg(&s1[lane + 64]);
    float4 u3 = __ldg(&s1[lane + 96]);

    float4* dst0 = out4 + ((long long)(row * t_out + f0) << 7);
    __stcs(&dst0[lane],      v0);
    __stcs(&dst0[lane + 32], v1);
    __stcs(&dst0[lane + 64], v2);
    __stcs(&dst0[lane + 96], v3);

    if (has2) {
        float4* dst1 = dst0 + C_DIM / 4;
        __stcs(&dst1[lane],      u0);
        __stcs(&dst1[lane + 32], u1);
        __stcs(&dst1[lane + 64], u2);
        __stcs(&dst1[lane + 96], u3);
    }
}

extern "C" void kernel_launch(void* const* d_in, const int* in_sizes, int n_in,
                              void* d_out, int out_size) {
    const float* x   = (const float*)d_in[0];
    const int*   dur = (const int*)d_in[1];
    float*       out = (float*)d_out;

    const int t_out = out_size / (B_DIM * C_DIM);

    dim3 grid((t_out + FRAMES_PER_BLOCK - 1) / FRAMES_PER_BLOCK, B_DIM);
    lr_fused_kernel<<<grid, 256>>>(
        (const float4*)x, (float4*)out, dur, t_out);
}

// round 16
// speedup vs baseline: 1.3787x; 1.3787x over previous
#include <cuda_runtime.h>
#include <stdint.h>

// Fixed problem shape (LengthRegulator_33285996544559):
//   x:   [B=32, T=512, C=512] float32
//   dur: [B=32, T=512] int32 in [0, 12)
//   out: [B, T_out, C] float32, T_out = out_size / (B*C)
//
// CONVERGED KERNEL — re-bench. R15's 50.7us on THIS IDENTICAL SOURCE came
// with HBM at 3.4 TB/s (vs 4.7 TB/s for the same binary in R9/R14): an
// environmental DVFS/neighbor state, not a kernel property. Plateau evidence
// (R4/R5/R9/R11/R14: 36.9-37.6us, DRAM ~59%, no other unit >50%) stands.
//
// Structure: fused single kernel, 256-thread blocks, 8 warps x 2 frames.
//   1) shfl pair-scan of the row's 512 durations (3 syncthreads)
//   2) scatter token ids into a 16-frame smem window
//   3) warp w gathers frames 2w, 2w+1: all 8 LDG.128 in flight before any
//      store (x is L2-resident); __stcs streaming stores.
#define B_DIM 32
#define T_DIM 512
#define C_DIM 512
#define FRAMES_PER_BLOCK 16   // 8 warps x 2 frames, 256 threads

__global__ void __launch_bounds__(256) lr_fused_kernel(
    const float4* __restrict__ x4,
    float4*       __restrict__ out4,
    const int*    __restrict__ dur,
    int t_out)
{
    __shared__ int s_wsum[8];
    __shared__ int s_idx[FRAMES_PER_BLOCK];

    const int row   = blockIdx.y;
    const int fbase = blockIdx.x * FRAMES_PER_BLOCK;
    const int tid   = threadIdx.x;
    const int wid   = tid >> 5;
    const int lane  = tid & 31;

    // ---- 1) scan: each thread owns a PAIR of durations (int2 load) ----
    int2 dd = ((const int2*)dur)[row * (T_DIM / 2) + tid];
    int d0 = dd.x > 0 ? dd.x : 0;
    int d1 = dd.y > 0 ? dd.y : 0;
    int p  = d0 + d1;

    int v = p;                                // intra-warp inclusive scan
    #pragma unroll
    for (int off = 1; off < 32; off <<= 1) {
        int n = __shfl_up_sync(0xffffffffu, v, off);
        if (lane >= off) v += n;
    }
    if (lane == 31) s_wsum[wid] = v;
    __syncthreads();
    if (wid == 0) {
        int w = (lane < 8) ? s_wsum[lane] : 0;
        #pragma unroll
        for (int off = 1; off < 8; off <<= 1) {
            int n = __shfl_up_sync(0xffffffffu, w, off);
            if (lane >= off) w += n;
        }
        if (lane < 8) s_wsum[lane] = w;
    }
    __syncthreads();

    const int pair_incl = ((wid > 0) ? s_wsum[wid - 1] : 0) + v;
    const int pair_excl = pair_incl - p;      // exclusive cumsum before token 2*tid
    const int total     = s_wsum[7];

    // token 2*tid   owns frames [pair_excl,    pair_excl+d0)
    // token 2*tid+1 owns frames [pair_excl+d0, pair_incl)

    // ---- 2) scatter into this block's frame window ----
    const int fend = fbase + FRAMES_PER_BLOCK;
    {
        int s = pair_excl, e = pair_excl + d0;
        int lo = s > fbase ? s : fbase;
        int hi = e < fend ? e : fend;
        for (int t = lo; t < hi; t++) s_idx[t - fbase] = 2 * tid;

        s = e; e = pair_incl;
        lo = s > fbase ? s : fbase;
        hi = e < fend ? e : fend;
        for (int t = lo; t < hi; t++) s_idx[t - fbase] = 2 * tid + 1;
    }
    if (tid < FRAMES_PER_BLOCK && (fbase + tid) >= total)
        s_idx[tid] = T_DIM - 1;               // overflow -> last token
    __syncthreads();

    // ---- 3) gather: warp w -> frames 2w, 2w+1 ----
    const int lf0 = wid << 1;
    const int f0  = fbase + lf0;
    if (f0 >= t_out) return;

    const bool has2 = (f0 + 1) < t_out;
    const int  i0 = s_idx[lf0];
    const int  i1 = s_idx[has2 ? lf0 + 1 : lf0];

    const float4* s0 = x4 + ((long long)(row * T_DIM + i0) << 7);
    const float4* s1 = x4 + ((long long)(row * T_DIM + i1) << 7);

    float4 v0 = __ldg(&s0[lane]);
    float4 v1 = __ldg(&s0[lane + 32]);
    float4 v2 = __ldg(&s0[lane + 64]);
    float4 v3 = __ldg(&s0[lane + 96]);
    float4 u0 = __ldg(&s1[lane]);
    float4 u1 = __ldg(&s1[lane + 32]);
    float4 u2 = __ldg(&s1[lane + 64]);
    float4 u3 = __ldg(&s1[lane + 96]);

    float4* dst0 = out4 + ((long long)(row * t_out + f0) << 7);
    __stcs(&dst0[lane],      v0);
    __stcs(&dst0[lane + 32], v1);
    __stcs(&dst0[lane + 64], v2);
    __stcs(&dst0[lane + 96], v3);

    if (has2) {
        float4* dst1 = dst0 + C_DIM / 4;
        __stcs(&dst1[lane],      u0);
        __stcs(&dst1[lane + 32], u1);
        __stcs(&dst1[lane + 64], u2);
        __stcs(&dst1[lane + 96], u3);
    }
}

extern "C" void kernel_launch(void* const* d_in, const int* in_sizes, int n_in,
                              void* d_out, int out_size) {
    const float* x   = (const float*)d_in[0];
    const int*   dur = (const int*)d_in[1];
    float*       out = (float*)d_out;

    const int t_out = out_size / (B_DIM * C_DIM);

    dim3 grid((t_out + FRAMES_PER_BLOCK - 1) / FRAMES_PER_BLOCK, B_DIM);
    lr_fused_kernel<<<grid, 256>>>(
        (const float4*)x, (float4*)out, dur, t_out);
}

// round 17
// speedup vs baseline: 1.3943x; 1.0113x over previous
#include <cuda_runtime.h>
#include <stdint.h>

// Fixed problem shape (LengthRegulator_33285996544559):
//   x:   [B=32, T=512, C=512] float32
//   dur: [B=32, T=512] int32 in [0, 12)
//   out: [B, T_out, C] float32, T_out = out_size / (B*C)
//
// FINAL CONVERGED KERNEL (16 rounds). Plateau: 36.9-37.6us across four
// independent structures; DRAM ~59% (4.7 TB/s), no other unit >50%.
// Binding resource: ~203 MB compulsory output write stream at ~5.5 TB/s
// effective mixed HBM bandwidth. Falsified: MLP>4, persistent blocks, PDL,
// barrier-free scan, stwt, TMA bulk stores, L2 read dedup (x2).
//
// Structure: fused single kernel, 256-thread blocks, 8 warps x 2 frames.
//   1) shfl pair-scan of the row's 512 durations (3 syncthreads)
//   2) scatter token ids into a 16-frame smem window
//   3) warp w gathers frames 2w, 2w+1: all 8 LDG.128 in flight before any
//      store (x is L2-resident); __stcs streaming stores.
#define B_DIM 32
#define T_DIM 512
#define C_DIM 512
#define FRAMES_PER_BLOCK 16   // 8 warps x 2 frames, 256 threads

__global__ void __launch_bounds__(256) lr_fused_kernel(
    const float4* __restrict__ x4,
    float4*       __restrict__ out4,
    const int*    __restrict__ dur,
    int t_out)
{
    __shared__ int s_wsum[8];
    __shared__ int s_idx[FRAMES_PER_BLOCK];

    const int row   = blockIdx.y;
    const int fbase = blockIdx.x * FRAMES_PER_BLOCK;
    const int tid   = threadIdx.x;
    const int wid   = tid >> 5;
    const int lane  = tid & 31;

    // ---- 1) scan: each thread owns a PAIR of durations (int2 load) ----
    int2 dd = ((const int2*)dur)[row * (T_DIM / 2) + tid];
    int d0 = dd.x > 0 ? dd.x : 0;
    int d1 = dd.y > 0 ? dd.y : 0;
    int p  = d0 + d1;

    int v = p;                                // intra-warp inclusive scan
    #pragma unroll
    for (int off = 1; off < 32; off <<= 1) {
        int n = __shfl_up_sync(0xffffffffu, v, off);
        if (lane >= off) v += n;
    }
    if (lane == 31) s_wsum[wid] = v;
    __syncthreads();
    if (wid == 0) {
        int w = (lane < 8) ? s_wsum[lane] : 0;
        #pragma unroll
        for (int off = 1; off < 8; off <<= 1) {
            int n = __shfl_up_sync(0xffffffffu, w, off);
            if (lane >= off) w += n;
        }
        if (lane < 8) s_wsum[lane] = w;
    }
    __syncthreads();

    const int pair_incl = ((wid > 0) ? s_wsum[wid - 1] : 0) + v;
    const int pair_excl = pair_incl - p;      // exclusive cumsum before token 2*tid
    const int total     = s_wsum[7];

    // token 2*tid   owns frames [pair_excl,    pair_excl+d0)
    // token 2*tid+1 owns frames [pair_excl+d0, pair_incl)

    // ---- 2) scatter into this block's frame window ----
    const int fend = fbase + FRAMES_PER_BLOCK;
    {
        int s = pair_excl, e = pair_excl + d0;
        int lo = s > fbase ? s : fbase;
        int hi = e < fend ? e : fend;
        for (int t = lo; t < hi; t++) s_idx[t - fbase] = 2 * tid;

        s = e; e = pair_incl;
        lo = s > fbase ? s : fbase;
        hi = e < fend ? e : fend;
        for (int t = lo; t < hi; t++) s_idx[t - fbase] = 2 * tid + 1;
    }
    if (tid < FRAMES_PER_BLOCK && (fbase + tid) >= total)
        s_idx[tid] = T_DIM - 1;               // overflow -> last token
    __syncthreads();

    // ---- 3) gather: warp w -> frames 2w, 2w+1 ----
    const int lf0 = wid << 1;
    const int f0  = fbase + lf0;
    if (f0 >= t_out) return;

    const bool has2 = (f0 + 1) < t_out;
    const int  i0 = s_idx[lf0];
    const int  i1 = s_idx[has2 ? lf0 + 1 : lf0];

    const float4* s0 = x4 + ((long long)(row * T_DIM + i0) << 7);
    const float4* s1 = x4 + ((long long)(row * T_DIM + i1) << 7);

    float4 v0 = __ldg(&s0[lane]);
    float4 v1 = __ldg(&s0[lane + 32]);
    float4 v2 = __ldg(&s0[lane + 64]);
    float4 v3 = __ldg(&s0[lane + 96]);
    float4 u0 = __ldg(&s1[lane]);
    float4 u1 = __ldg(&s1[lane + 32]);
    float4 u2 = __ldg(&s1[lane + 64]);
    float4 u3 = __ldg(&s1[lane + 96]);

    float4* dst0 = out4 + ((long long)(row * t_out + f0) << 7);
    __stcs(&dst0[lane],      v0);
    __stcs(&dst0[lane + 32], v1);
    __stcs(&dst0[lane + 64], v2);
    __stcs(&dst0[lane + 96], v3);

    if (has2) {
        float4* dst1 = dst0 + C_DIM / 4;
        __stcs(&dst1[lane],      u0);
        __stcs(&dst1[lane + 32], u1);
        __stcs(&dst1[lane + 64], u2);
        __stcs(&dst1[lane + 96], u3);
    }
}

extern "C" void kernel_launch(void* const* d_in, const int* in_sizes, int n_in,
                              void* d_out, int out_size) {
    const float* x   = (const float*)d_in[0];
    const int*   dur = (const int*)d_in[1];
    float*       out = (float*)d_out;

    const int t_out = out_size / (B_DIM * C_DIM);

    dim3 grid((t_out + FRAMES_PER_BLOCK - 1) / FRAMES_PER_BLOCK, B_DIM);
    lr_fused_kernel<<<grid, 256>>>(
        (const float4*)x, (float4*)out, dur, t_out);
}